// round 3
// baseline (speedup 1.0000x reference)
#include <cuda_runtime.h>
#include <cstdint>

typedef unsigned long long u64;

#define BB 512
#define SS 512
#define FF 64
#define HH 128
#define GG 512   // 4*H
#define OO 64

// ---- scratch (static __device__ globals: allocation-free rule) ----
__device__ float g_xp[(size_t)BB * SS * GG];   // 512 MB, reused across layers
__device__ float g_h0[(size_t)BB * SS * HH];   // 64 MB  (layer0 hidden sequence)
__device__ float g_h1[BB * HH];                // layer1 last hidden

// ---- packed f32x2 helpers (sm_103a FFMA2 path) ----
__device__ __forceinline__ u64 ffma2(u64 a, u64 b, u64 c) {
    u64 d; asm("fma.rn.f32x2 %0,%1,%2,%3;" : "=l"(d) : "l"(a), "l"(b), "l"(c)); return d;
}
__device__ __forceinline__ u64 pack2(float x) {
    u64 d; asm("mov.b64 %0,{%1,%1};" : "=l"(d) : "f"(x)); return d;
}
__device__ __forceinline__ float2 unpack2(u64 v) {
    float2 r; asm("mov.b64 {%0,%1},%2;" : "=f"(r.x), "=f"(r.y) : "l"(v)); return r;
}

__device__ __forceinline__ float sigf(float x) {
    return __fdividef(1.0f, 1.0f + __expf(-x));
}
__device__ __forceinline__ float tanhf_fast(float x) {
    return 1.0f - __fdividef(2.0f, __expf(2.0f * x) + 1.0f);
}

// =====================================================================
// Projection GEMM (FFMA2, m-paired accumulators):
// out[M,512] = A[M,K] @ W[512,K]^T + ba + bb
// grid = (M/64, 2), block = 256 (thread = 8m x 8n outputs).
// SMEM: As[K][64], Ws4[K/4][256] (float4 = 4 consecutive k of one n-row)
// =====================================================================
template <int K>
__global__ __launch_bounds__(256) void proj_kernel(
    const float* __restrict__ A, const float* __restrict__ W,
    const float* __restrict__ ba, const float* __restrict__ bb,
    float* __restrict__ out)
{
    extern __shared__ float sm[];
    float* As   = sm;                       // [K][64]
    float4* Ws4 = (float4*)(sm + K * 64);   // [K/4][256]

    const int tid = threadIdx.x;
    const int m0 = blockIdx.x * 64;
    const int n0 = blockIdx.y * 256;

    // fill Ws4: thread walks its own n-row (STS conflict-free)
    {
        const float4* wr = (const float4*)(W + (size_t)(n0 + tid) * K);
        #pragma unroll 4
        for (int k4 = 0; k4 < K / 4; k4++)
            Ws4[k4 * 256 + tid] = wr[k4];
    }
    // fill As: LDG.128 along k, scatter scalar STS (lanes = consecutive m)
    for (int e = tid; e < 64 * (K / 4); e += 256) {
        int m = e & 63, k4 = e >> 6;
        float4 a = *(const float4*)(A + (size_t)(m0 + m) * K + k4 * 4);
        As[(k4 * 4 + 0) * 64 + m] = a.x;
        As[(k4 * 4 + 1) * 64 + m] = a.y;
        As[(k4 * 4 + 2) * 64 + m] = a.z;
        As[(k4 * 4 + 3) * 64 + m] = a.w;
    }
    __syncthreads();

    const int mb = (tid >> 5) * 8;   // 8 m-rows (4 packed pairs)
    const int nb = (tid & 31) * 8;   // 8 n-cols

    u64 acc[4][8];
    #pragma unroll
    for (int p = 0; p < 4; p++)
        #pragma unroll
        for (int j = 0; j < 8; j++) acc[p][j] = 0ull;

    for (int k4 = 0; k4 < K / 4; k4++) {
        float4 w[8];
        #pragma unroll
        for (int j = 0; j < 8; j++) w[j] = Ws4[k4 * 256 + nb + j];
        #pragma unroll
        for (int kk = 0; kk < 4; kk++) {
            const int k = k4 * 4 + kk;
            ulonglong2 aA = *(const ulonglong2*)(As + k * 64 + mb);      // {m0,m1},{m2,m3}
            ulonglong2 aB = *(const ulonglong2*)(As + k * 64 + mb + 4);  // {m4,m5},{m6,m7}
            u64 ap[4] = {aA.x, aA.y, aB.x, aB.y};
            #pragma unroll
            for (int j = 0; j < 8; j++) {
                float ws = (kk == 0) ? w[j].x : (kk == 1) ? w[j].y : (kk == 2) ? w[j].z : w[j].w;
                u64 wp = pack2(ws);
                #pragma unroll
                for (int p = 0; p < 4; p++)
                    acc[p][j] = ffma2(ap[p], wp, acc[p][j]);
            }
        }
    }

    float bias[8];
    #pragma unroll
    for (int j = 0; j < 8; j++)
        bias[j] = ba[n0 + nb + j] + bb[n0 + nb + j];

    #pragma unroll
    for (int p = 0; p < 4; p++) {
        float r0[8], r1[8];
        #pragma unroll
        for (int j = 0; j < 8; j++) {
            float2 v = unpack2(acc[p][j]);
            r0[j] = v.x + bias[j];
            r1[j] = v.y + bias[j];
        }
        float* o0 = out + (size_t)(m0 + mb + 2 * p) * GG + n0 + nb;
        float* o1 = o0 + GG;
        *(float4*)(o0)     = make_float4(r0[0], r0[1], r0[2], r0[3]);
        *(float4*)(o0 + 4) = make_float4(r0[4], r0[5], r0[6], r0[7]);
        *(float4*)(o1)     = make_float4(r1[0], r1[1], r1[2], r1[3]);
        *(float4*)(o1 + 4) = make_float4(r1[4], r1[5], r1[6], r1[7]);
    }
}

// =====================================================================
// Recurrent LSTM layer (FFMA2, W_hh resident in REGISTERS).
// cluster = 2 CTAs, 8 batch rows per cluster; CTA owns 64 hidden cols
// (256 gate rows). Thread = 2 gate rows x 32 k (k-quarter) -> 64 W regs.
// h replicated per CTA (double-buffered, broadcast LDS). Partials via gsm.
// grid = 128 CTAs (64 clusters), block = 512.
// =====================================================================
__global__ void __cluster_dims__(2, 1, 1) __launch_bounds__(512, 1) lstm_kernel(
    const float* __restrict__ xp,    // [B, S, 4H]
    const float* __restrict__ W_hh,  // [4H, H]
    float* __restrict__ hseq,        // [B, S, H]  (layer 0)
    float* __restrict__ hlast,       // [B, H]     (layer 1)
    int store_seq)
{
    extern __shared__ float sm[];
    float* hsm = sm;          // 2 x [2 grp][128 k][4 b] = 2 x 1024
    float* gsm = sm + 2048;   // [4 kq][256 r][stride 9] = 9216

    const int tid    = threadIdx.x;
    const int rank   = blockIdx.x & 1;
    const int peer   = rank ^ 1;
    const int batch0 = (blockIdx.x >> 1) * 8;

    const int kq = tid >> 7;         // k-quarter 0..3
    const int rr = tid & 127;        // local row-pair id
    const int grow0 = (rr >> 6) * 128 + rank * 64 + (rr & 63);
    const int grow1 = grow0 + 256;

    // ---- W slice into registers (once) ----
    float w0[32], w1[32];
    {
        const float4* p0 = (const float4*)(W_hh + (size_t)grow0 * HH + kq * 32);
        const float4* p1 = (const float4*)(W_hh + (size_t)grow1 * HH + kq * 32);
        #pragma unroll
        for (int j = 0; j < 8; j++) {
            float4 v0 = p0[j];
            float4 v1 = p1[j];
            w0[j * 4 + 0] = v0.x; w0[j * 4 + 1] = v0.y; w0[j * 4 + 2] = v0.z; w0[j * 4 + 3] = v0.w;
            w1[j * 4 + 0] = v1.x; w1[j * 4 + 1] = v1.y; w1[j * 4 + 2] = v1.z; w1[j * 4 + 3] = v1.w;
        }
    }
    for (int i = tid; i < 2048; i += 512) hsm[i] = 0.0f;

    asm volatile("barrier.cluster.arrive.aligned;\n" ::: "memory");
    asm volatile("barrier.cluster.wait.aligned;\n" ::: "memory");

    // update mapping: one (col, batch) per thread
    const int ub  = tid >> 6;        // batch 0..7
    const int ucl = tid & 63;        // local col
    const int col = rank * 64 + ucl;

    float creg = 0.0f;
    int buf = 0;

    for (int s = 0; s < SS; s++) {
        const float* Hc = hsm + buf * 1024 + kq * 128;  // this thread's k-quarter base
        float* Hn = hsm + (buf ^ 1) * 1024;

        // prefetch this step's x-projection (used after GEMM)
        float xv[4];
        {
            const float* xpp = xp + ((size_t)(batch0 + ub) * SS + s) * GG + rank * 64 + ucl;
            #pragma unroll
            for (int gt = 0; gt < 4; gt++) xv[gt] = xpp[gt * 128];
        }

        // ---- partial gate GEMM: 2 rows x 32 k x 8 batch, W in regs
        u64 a00 = 0, a01 = 0, a02 = 0, a03 = 0;
        u64 a10 = 0, a11 = 0, a12 = 0, a13 = 0;

        #pragma unroll
        for (int k = 0; k < 32; k++) {
            ulonglong2 hA = *(const ulonglong2*)(Hc + k * 4);        // b0..b3 (broadcast)
            ulonglong2 hB = *(const ulonglong2*)(Hc + 512 + k * 4);  // b4..b7
            u64 wp0 = pack2(w0[k]);
            u64 wp1 = pack2(w1[k]);
            a00 = ffma2(hA.x, wp0, a00);
            a01 = ffma2(hA.y, wp0, a01);
            a02 = ffma2(hB.x, wp0, a02);
            a03 = ffma2(hB.y, wp0, a03);
            a10 = ffma2(hA.x, wp1, a10);
            a11 = ffma2(hA.y, wp1, a11);
            a12 = ffma2(hB.x, wp1, a12);
            a13 = ffma2(hB.y, wp1, a13);
        }

        // write partials: gsm[kq][row][b]
        {
            float* g0 = gsm + kq * 2304 + rr * 9;
            float* g1 = gsm + kq * 2304 + (rr + 128) * 9;
            float2 v;
            v = unpack2(a00); g0[0] = v.x; g0[1] = v.y;
            v = unpack2(a01); g0[2] = v.x; g0[3] = v.y;
            v = unpack2(a02); g0[4] = v.x; g0[5] = v.y;
            v = unpack2(a03); g0[6] = v.x; g0[7] = v.y;
            v = unpack2(a10); g1[0] = v.x; g1[1] = v.y;
            v = unpack2(a11); g1[2] = v.x; g1[3] = v.y;
            v = unpack2(a12); g1[4] = v.x; g1[5] = v.y;
            v = unpack2(a13); g1[6] = v.x; g1[7] = v.y;
        }
        __syncthreads();

        // ---- nonlinearity + state update: thread -> (col, batch ub)
        {
            float g4[4];
            #pragma unroll
            for (int gt = 0; gt < 4; gt++) {
                const int row = gt * 64 + ucl;
                float v = xv[gt];
                v += gsm[row * 9 + ub];
                v += gsm[2304 + row * 9 + ub];
                v += gsm[4608 + row * 9 + ub];
                v += gsm[6912 + row * 9 + ub];
                g4[gt] = v;
            }
            float iv = sigf(g4[0]);
            float fv = sigf(g4[1]);
            float gv = tanhf_fast(g4[2]);
            float ov = sigf(g4[3]);
            creg = fmaf(fv, creg, iv * gv);
            float hh = ov * tanhf_fast(creg);

            const int hoff = (ub >> 2) * 512 + col * 4 + (ub & 3);
            Hn[hoff] = hh;
            uint32_t la = (uint32_t)__cvta_generic_to_shared(Hn + hoff);
            uint32_t ra;
            asm("mapa.shared::cluster.u32 %0, %1, %2;" : "=r"(ra) : "r"(la), "r"(peer));
            asm volatile("st.shared::cluster.f32 [%0], %1;" :: "r"(ra), "f"(hh) : "memory");

            if (store_seq) {
                hseq[((size_t)(batch0 + ub) * SS + s) * HH + col] = hh;
            } else if (s == SS - 1) {
                hlast[(batch0 + ub) * HH + col] = hh;
            }
        }

        asm volatile("barrier.cluster.arrive.aligned;\n" ::: "memory");
        asm volatile("barrier.cluster.wait.aligned;\n" ::: "memory");
        buf ^= 1;
    }
}

// =====================================================================
// Final FC: out[b,o] = relu(h1[b,:]) @ fc_w[o,:] + fc_b[o]
// =====================================================================
__global__ __launch_bounds__(64) void fc_kernel(
    const float* __restrict__ h1, const float* __restrict__ fcw,
    const float* __restrict__ fcb, float* __restrict__ out)
{
    __shared__ float hs[HH];
    const int b = blockIdx.x;
    const int o = threadIdx.x;
    hs[o]      = fmaxf(h1[b * HH + o], 0.0f);
    hs[o + 64] = fmaxf(h1[b * HH + o + 64], 0.0f);
    __syncthreads();
    float acc = fcb[o];
    const float* wr = fcw + o * HH;
    #pragma unroll 8
    for (int k = 0; k < HH; k++)
        acc = fmaf(hs[k], wr[k], acc);
    out[b * OO + o] = acc;
}

// =====================================================================
extern "C" void kernel_launch(void* const* d_in, const int* in_sizes, int n_in,
                              void* d_out, int out_size)
{
    (void)in_sizes; (void)n_in; (void)out_size;
    const float* x     = (const float*)d_in[0];
    const float* W_ih0 = (const float*)d_in[1];
    const float* W_hh0 = (const float*)d_in[2];
    const float* b_ih0 = (const float*)d_in[3];
    const float* b_hh0 = (const float*)d_in[4];
    const float* W_ih1 = (const float*)d_in[5];
    const float* W_hh1 = (const float*)d_in[6];
    const float* b_ih1 = (const float*)d_in[7];
    const float* b_hh1 = (const float*)d_in[8];
    const float* fc_w  = (const float*)d_in[9];
    const float* fc_b  = (const float*)d_in[10];
    float* out = (float*)d_out;

    float *xp, *h0, *h1;
    cudaGetSymbolAddress((void**)&xp, g_xp);
    cudaGetSymbolAddress((void**)&h0, g_h0);
    cudaGetSymbolAddress((void**)&h1, g_h1);

    const int PROJ0_SMEM = 64 * FF * 4 + (FF / 4) * 256 * 16;   // 81920
    const int PROJ1_SMEM = 64 * HH * 4 + (HH / 4) * 256 * 16;   // 163840
    const int LSTM_SMEM  = (2048 + 9216) * 4;                   // 45056

    cudaFuncSetAttribute(proj_kernel<FF>, cudaFuncAttributeMaxDynamicSharedMemorySize, PROJ0_SMEM);
    cudaFuncSetAttribute(proj_kernel<HH>, cudaFuncAttributeMaxDynamicSharedMemorySize, PROJ1_SMEM);
    cudaFuncSetAttribute(lstm_kernel, cudaFuncAttributeMaxDynamicSharedMemorySize, LSTM_SMEM);

    dim3 pgrid((BB * SS) / 64, 2);

    // Layer 0
    proj_kernel<FF><<<pgrid, 256, PROJ0_SMEM>>>(x, W_ih0, b_ih0, b_hh0, xp);
    lstm_kernel<<<128, 512, LSTM_SMEM>>>(xp, W_hh0, h0, nullptr, 1);

    // Layer 1
    proj_kernel<HH><<<pgrid, 256, PROJ1_SMEM>>>(h0, W_ih1, b_ih1, b_hh1, xp);
    lstm_kernel<<<128, 512, LSTM_SMEM>>>(xp, W_hh1, nullptr, h1, 0);

    // FC head
    fc_kernel<<<BB, 64>>>(h1, fc_w, fc_b, out);
}

// round 4
// speedup vs baseline: 1.2946x; 1.2946x over previous
#include <cuda_runtime.h>
#include <cstdint>

typedef unsigned long long u64;

#define BB 512
#define SS 512
#define FF 64
#define HH 128
#define GG 512   // 4*H
#define OO 64

// ---- scratch (static __device__ globals: allocation-free rule) ----
__device__ float g_xp[(size_t)BB * SS * GG];   // 512 MB, reused across layers
__device__ float g_h0[(size_t)BB * SS * HH];   // 64 MB  (layer0 hidden sequence)
__device__ float g_h1[BB * HH];                // layer1 last hidden

// ---- packed f32x2 helpers (sm_103a FFMA2 path) ----
__device__ __forceinline__ u64 ffma2(u64 a, u64 b, u64 c) {
    u64 d; asm("fma.rn.f32x2 %0,%1,%2,%3;" : "=l"(d) : "l"(a), "l"(b), "l"(c)); return d;
}
__device__ __forceinline__ u64 pack2(float x) {
    u64 d; asm("mov.b64 %0,{%1,%1};" : "=l"(d) : "f"(x)); return d;
}
__device__ __forceinline__ float2 unpack2(u64 v) {
    float2 r; asm("mov.b64 {%0,%1},%2;" : "=f"(r.x), "=f"(r.y) : "l"(v)); return r;
}

__device__ __forceinline__ float sigf(float x) {
    return __fdividef(1.0f, 1.0f + __expf(-x));
}
__device__ __forceinline__ float tanhf_fast(float x) {
    return 1.0f - __fdividef(2.0f, __expf(2.0f * x) + 1.0f);
}

// =====================================================================
// Projection GEMM (FFMA2, double-buffered 16-k chunks, 2 CTAs/SM):
// out[M,512] = A[M,K] @ W[512,K]^T + ba + bb
// grid = (M/128, 4), block = 256 (thread = 8m x 8n).
// SMEM: smA[2][16][136], smW[2][16][136]  (k-major, padded rows)
// =====================================================================
#define KPAD 136
#define TBUF (16 * KPAD)   // 2176 floats per buffer

template <int K>
__global__ __launch_bounds__(256, 2) void proj_kernel(
    const float* __restrict__ A, const float* __restrict__ W,
    const float* __restrict__ ba, const float* __restrict__ bb,
    float* __restrict__ out)
{
    extern __shared__ float sm[];
    float* smA = sm;               // 2 x TBUF
    float* smW = sm + 2 * TBUF;    // 2 x TBUF

    const int tid = threadIdx.x;
    const int m0 = blockIdx.x * 128;
    const int n0 = blockIdx.y * 128;
    const int NC = K / 16;

    const int rl = tid >> 2;       // load row 0..63
    const int k4 = tid & 3;        // k-quad within chunk

    // chunk 0 fill
    {
        float4 a0 = *(const float4*)(A + (size_t)(m0 + rl) * K + k4 * 4);
        float4 a1 = *(const float4*)(A + (size_t)(m0 + rl + 64) * K + k4 * 4);
        float4 w0 = *(const float4*)(W + (size_t)(n0 + rl) * K + k4 * 4);
        float4 w1 = *(const float4*)(W + (size_t)(n0 + rl + 64) * K + k4 * 4);
        #pragma unroll
        for (int j = 0; j < 4; j++) {
            float av0 = (j==0)?a0.x:(j==1)?a0.y:(j==2)?a0.z:a0.w;
            float av1 = (j==0)?a1.x:(j==1)?a1.y:(j==2)?a1.z:a1.w;
            float wv0 = (j==0)?w0.x:(j==1)?w0.y:(j==2)?w0.z:w0.w;
            float wv1 = (j==0)?w1.x:(j==1)?w1.y:(j==2)?w1.z:w1.w;
            smA[(k4*4+j)*KPAD + rl]      = av0;
            smA[(k4*4+j)*KPAD + rl + 64] = av1;
            smW[(k4*4+j)*KPAD + rl]      = wv0;
            smW[(k4*4+j)*KPAD + rl + 64] = wv1;
        }
    }
    __syncthreads();

    const int mb = (tid >> 4) * 8;   // m-octet
    const int nb = (tid & 15) * 8;   // n-octet

    u64 acc[4][8];
    #pragma unroll
    for (int p = 0; p < 4; p++)
        #pragma unroll
        for (int j = 0; j < 8; j++) acc[p][j] = 0ull;

    int buf = 0;
    for (int c = 0; c < NC; c++) {
        float4 pa0, pa1, pw0, pw1;
        const bool pf = (c + 1 < NC);
        if (pf) {
            const int k0 = (c + 1) * 16;
            pa0 = *(const float4*)(A + (size_t)(m0 + rl) * K + k0 + k4 * 4);
            pa1 = *(const float4*)(A + (size_t)(m0 + rl + 64) * K + k0 + k4 * 4);
            pw0 = *(const float4*)(W + (size_t)(n0 + rl) * K + k0 + k4 * 4);
            pw1 = *(const float4*)(W + (size_t)(n0 + rl + 64) * K + k0 + k4 * 4);
        }

        const float* bA = smA + buf * TBUF;
        const float* bW = smW + buf * TBUF;
        #pragma unroll
        for (int kk = 0; kk < 16; kk++) {
            ulonglong2 aA = *(const ulonglong2*)(bA + kk * KPAD + mb);
            ulonglong2 aB = *(const ulonglong2*)(bA + kk * KPAD + mb + 4);
            float4 w0 = *(const float4*)(bW + kk * KPAD + nb);
            float4 w1 = *(const float4*)(bW + kk * KPAD + nb + 4);
            u64 ap[4] = {aA.x, aA.y, aB.x, aB.y};
            float wf[8] = {w0.x, w0.y, w0.z, w0.w, w1.x, w1.y, w1.z, w1.w};
            #pragma unroll
            for (int j = 0; j < 8; j++) {
                u64 wp = pack2(wf[j]);
                #pragma unroll
                for (int p = 0; p < 4; p++)
                    acc[p][j] = ffma2(ap[p], wp, acc[p][j]);
            }
        }

        if (pf) {
            float* dA = smA + (buf ^ 1) * TBUF;
            float* dW = smW + (buf ^ 1) * TBUF;
            #pragma unroll
            for (int j = 0; j < 4; j++) {
                float av0 = (j==0)?pa0.x:(j==1)?pa0.y:(j==2)?pa0.z:pa0.w;
                float av1 = (j==0)?pa1.x:(j==1)?pa1.y:(j==2)?pa1.z:pa1.w;
                float wv0 = (j==0)?pw0.x:(j==1)?pw0.y:(j==2)?pw0.z:pw0.w;
                float wv1 = (j==0)?pw1.x:(j==1)?pw1.y:(j==2)?pw1.z:pw1.w;
                dA[(k4*4+j)*KPAD + rl]      = av0;
                dA[(k4*4+j)*KPAD + rl + 64] = av1;
                dW[(k4*4+j)*KPAD + rl]      = wv0;
                dW[(k4*4+j)*KPAD + rl + 64] = wv1;
            }
        }
        __syncthreads();
        buf ^= 1;
    }

    float bias[8];
    #pragma unroll
    for (int j = 0; j < 8; j++)
        bias[j] = ba[n0 + nb + j] + bb[n0 + nb + j];

    #pragma unroll
    for (int p = 0; p < 4; p++) {
        float r0[8], r1[8];
        #pragma unroll
        for (int j = 0; j < 8; j++) {
            float2 v = unpack2(acc[p][j]);
            r0[j] = v.x + bias[j];
            r1[j] = v.y + bias[j];
        }
        float* o0 = out + (size_t)(m0 + mb + 2 * p) * GG + n0 + nb;
        float* o1 = o0 + GG;
        *(float4*)(o0)     = make_float4(r0[0], r0[1], r0[2], r0[3]);
        *(float4*)(o0 + 4) = make_float4(r0[4], r0[5], r0[6], r0[7]);
        *(float4*)(o1)     = make_float4(r1[0], r1[1], r1[2], r1[3]);
        *(float4*)(o1 + 4) = make_float4(r1[4], r1[5], r1[6], r1[7]);
    }
}

// =====================================================================
// Recurrent LSTM layer (FFMA2, W_hh in registers, 1024 threads).
// cluster = 2 CTAs, 8 batch rows per cluster; CTA owns 64 hidden cols
// (256 gate rows). Thread = 1 gate row x 32 k (k-quarter): 32 W regs,
// 4 u64 accumulators. Partials (4 k-quarters) reduced via gsm.
// grid = 128 CTAs (64 clusters), block = 1024.
// =====================================================================
__global__ void __cluster_dims__(2, 1, 1) __launch_bounds__(1024, 1) lstm_kernel(
    const float* __restrict__ xp,    // [B, S, 4H]
    const float* __restrict__ W_hh,  // [4H, H]
    float* __restrict__ hseq,        // [B, S, H]  (layer 0)
    float* __restrict__ hlast,       // [B, H]     (layer 1)
    int store_seq)
{
    extern __shared__ float sm[];
    float* hsm = sm;          // 2 x [2 grp][128 k][4 b] = 2 x 1024
    float* gsm = sm + 2048;   // [4 kq][256 r][stride 9] = 9216

    const int tid    = threadIdx.x;
    const int rank   = blockIdx.x & 1;
    const int peer   = rank ^ 1;
    const int batch0 = (blockIdx.x >> 1) * 8;

    const int kq = tid >> 8;         // k-quarter 0..3
    const int r  = tid & 255;        // local gate row 0..255
    const int grow = (r >> 6) * 128 + rank * 64 + (r & 63);

    // ---- W slice into registers (once): 32 floats
    float w[32];
    {
        const float4* p = (const float4*)(W_hh + (size_t)grow * HH + kq * 32);
        #pragma unroll
        for (int j = 0; j < 8; j++) {
            float4 v = p[j];
            w[4*j+0] = v.x; w[4*j+1] = v.y; w[4*j+2] = v.z; w[4*j+3] = v.w;
        }
    }
    for (int i = tid; i < 2048; i += 1024) hsm[i] = 0.0f;

    asm volatile("barrier.cluster.arrive.aligned;\n" ::: "memory");
    asm volatile("barrier.cluster.wait.aligned;\n" ::: "memory");

    // update mapping (tid < 512): one (col, batch) per thread
    const int ub  = tid >> 6;        // batch 0..7 (valid for tid<512)
    const int ucl = tid & 63;        // local col
    const int col = rank * 64 + ucl;

    float creg = 0.0f;
    int buf = 0;

    for (int s = 0; s < SS; s++) {
        const float* Hc = hsm + buf * 1024;
        float* Hn = hsm + (buf ^ 1) * 1024;

        // prefetch x-projection for update phase
        float xv0, xv1, xv2, xv3;
        if (tid < 512) {
            const float* xpp = xp + ((size_t)(batch0 + ub) * SS + s) * GG + rank * 64 + ucl;
            xv0 = xpp[0];
            xv1 = xpp[128];
            xv2 = xpp[256];
            xv3 = xpp[384];
        }

        // ---- partial gate GEMM: 1 row x 32 k x 8 batch
        u64 a0 = 0, a1 = 0, a2 = 0, a3 = 0;
        {
            const float* Hq = Hc + kq * 128;   // k base (col*4 addressing, kq*32 cols)
            #pragma unroll
            for (int kk = 0; kk < 32; kk++) {
                ulonglong2 hA = *(const ulonglong2*)(Hq + kk * 4);        // b0..b3
                ulonglong2 hB = *(const ulonglong2*)(Hq + 512 + kk * 4);  // b4..b7
                u64 wp = pack2(w[kk]);
                a0 = ffma2(hA.x, wp, a0);
                a1 = ffma2(hA.y, wp, a1);
                a2 = ffma2(hB.x, wp, a2);
                a3 = ffma2(hB.y, wp, a3);
            }
        }
        {
            float* g = gsm + kq * 2304 + r * 9;
            float2 v;
            v = unpack2(a0); g[0] = v.x; g[1] = v.y;
            v = unpack2(a1); g[2] = v.x; g[3] = v.y;
            v = unpack2(a2); g[4] = v.x; g[5] = v.y;
            v = unpack2(a3); g[6] = v.x; g[7] = v.y;
        }
        __syncthreads();

        // ---- nonlinearity + state update (tid < 512)
        if (tid < 512) {
            float g4[4] = {xv0, xv1, xv2, xv3};
            #pragma unroll
            for (int gt = 0; gt < 4; gt++) {
                const int row = gt * 64 + ucl;
                g4[gt] += gsm[row * 9 + ub];
                g4[gt] += gsm[2304 + row * 9 + ub];
                g4[gt] += gsm[4608 + row * 9 + ub];
                g4[gt] += gsm[6912 + row * 9 + ub];
            }
            float iv = sigf(g4[0]);
            float fv = sigf(g4[1]);
            float gv = tanhf_fast(g4[2]);
            float ov = sigf(g4[3]);
            creg = fmaf(fv, creg, iv * gv);
            float hh = ov * tanhf_fast(creg);

            const int hoff = (ub >> 2) * 512 + col * 4 + (ub & 3);
            Hn[hoff] = hh;
            uint32_t la = (uint32_t)__cvta_generic_to_shared(Hn + hoff);
            uint32_t ra;
            asm("mapa.shared::cluster.u32 %0, %1, %2;" : "=r"(ra) : "r"(la), "r"(peer));
            asm volatile("st.shared::cluster.f32 [%0], %1;" :: "r"(ra), "f"(hh) : "memory");

            if (store_seq) {
                hseq[((size_t)(batch0 + ub) * SS + s) * HH + col] = hh;
            } else if (s == SS - 1) {
                hlast[(batch0 + ub) * HH + col] = hh;
            }
        }

        asm volatile("barrier.cluster.arrive.aligned;\n" ::: "memory");
        asm volatile("barrier.cluster.wait.aligned;\n" ::: "memory");
        buf ^= 1;
    }
}

// =====================================================================
// Final FC: out[b,o] = relu(h1[b,:]) @ fc_w[o,:] + fc_b[o]
// =====================================================================
__global__ __launch_bounds__(64) void fc_kernel(
    const float* __restrict__ h1, const float* __restrict__ fcw,
    const float* __restrict__ fcb, float* __restrict__ out)
{
    __shared__ float hs[HH];
    const int b = blockIdx.x;
    const int o = threadIdx.x;
    hs[o]      = fmaxf(h1[b * HH + o], 0.0f);
    hs[o + 64] = fmaxf(h1[b * HH + o + 64], 0.0f);
    __syncthreads();
    float acc = fcb[o];
    const float* wr = fcw + o * HH;
    #pragma unroll 8
    for (int k = 0; k < HH; k++)
        acc = fmaf(hs[k], wr[k], acc);
    out[b * OO + o] = acc;
}

// =====================================================================
extern "C" void kernel_launch(void* const* d_in, const int* in_sizes, int n_in,
                              void* d_out, int out_size)
{
    (void)in_sizes; (void)n_in; (void)out_size;
    const float* x     = (const float*)d_in[0];
    const float* W_ih0 = (const float*)d_in[1];
    const float* W_hh0 = (const float*)d_in[2];
    const float* b_ih0 = (const float*)d_in[3];
    const float* b_hh0 = (const float*)d_in[4];
    const float* W_ih1 = (const float*)d_in[5];
    const float* W_hh1 = (const float*)d_in[6];
    const float* b_ih1 = (const float*)d_in[7];
    const float* b_hh1 = (const float*)d_in[8];
    const float* fc_w  = (const float*)d_in[9];
    const float* fc_b  = (const float*)d_in[10];
    float* out = (float*)d_out;

    float *xp, *h0, *h1;
    cudaGetSymbolAddress((void**)&xp, g_xp);
    cudaGetSymbolAddress((void**)&h0, g_h0);
    cudaGetSymbolAddress((void**)&h1, g_h1);

    const int PROJ_SMEM = 4 * TBUF * 4;             // 34816
    const int LSTM_SMEM = (2048 + 9216) * 4;        // 45056

    cudaFuncSetAttribute(proj_kernel<FF>, cudaFuncAttributeMaxDynamicSharedMemorySize, PROJ_SMEM);
    cudaFuncSetAttribute(proj_kernel<HH>, cudaFuncAttributeMaxDynamicSharedMemorySize, PROJ_SMEM);
    cudaFuncSetAttribute(lstm_kernel, cudaFuncAttributeMaxDynamicSharedMemorySize, LSTM_SMEM);

    dim3 pgrid((BB * SS) / 128, GG / 128);

    // Layer 0
    proj_kernel<FF><<<pgrid, 256, PROJ_SMEM>>>(x, W_ih0, b_ih0, b_hh0, xp);
    lstm_kernel<<<128, 1024, LSTM_SMEM>>>(xp, W_hh0, h0, nullptr, 1);

    // Layer 1
    proj_kernel<HH><<<pgrid, 256, PROJ_SMEM>>>(h0, W_ih1, b_ih1, b_hh1, xp);
    lstm_kernel<<<128, 1024, LSTM_SMEM>>>(xp, W_hh1, nullptr, h1, 0);

    // FC head
    fc_kernel<<<BB, 64>>>(h1, fc_w, fc_b, out);
}

// round 5
// speedup vs baseline: 1.5723x; 1.2145x over previous
#include <cuda_runtime.h>
#include <cstdint>

typedef unsigned long long u64;

#define BB 512
#define SS 512
#define FF 64
#define HH 128
#define GG 512   // 4*H
#define OO 64

// ---- scratch (static __device__ globals: allocation-free rule) ----
__device__ float g_xp[(size_t)BB * SS * GG];   // 512 MB, reused across layers
__device__ float g_h0[(size_t)BB * SS * HH];   // 64 MB  (layer0 hidden sequence)
__device__ float g_h1[BB * HH];                // layer1 last hidden

// ---- packed f32x2 helpers (sm_103a FFMA2 path) ----
__device__ __forceinline__ u64 ffma2(u64 a, u64 b, u64 c) {
    u64 d; asm("fma.rn.f32x2 %0,%1,%2,%3;" : "=l"(d) : "l"(a), "l"(b), "l"(c)); return d;
}
__device__ __forceinline__ u64 pack2(float x) {
    u64 d; asm("mov.b64 %0,{%1,%1};" : "=l"(d) : "f"(x)); return d;
}
__device__ __forceinline__ float2 unpack2(u64 v) {
    float2 r; asm("mov.b64 {%0,%1},%2;" : "=f"(r.x), "=f"(r.y) : "l"(v)); return r;
}

__device__ __forceinline__ float sigf(float x) {
    return __fdividef(1.0f, 1.0f + __expf(-x));
}
__device__ __forceinline__ float tanhf_fast(float x) {
    return 1.0f - __fdividef(2.0f, __expf(2.0f * x) + 1.0f);
}

// =====================================================================
// Projection GEMM (FFMA2, double-buffered 16-k chunks, 2 CTAs/SM):
// out[M,512] = A[M,K] @ W[512,K]^T + ba + bb
// grid = (M/128, 4), block = 256 (thread = 8m x 8n).
// =====================================================================
#define KPAD 136
#define TBUF (16 * KPAD)   // 2176 floats per buffer

template <int K>
__global__ __launch_bounds__(256, 2) void proj_kernel(
    const float* __restrict__ A, const float* __restrict__ W,
    const float* __restrict__ ba, const float* __restrict__ bb,
    float* __restrict__ out)
{
    extern __shared__ float sm[];
    float* smA = sm;               // 2 x TBUF
    float* smW = sm + 2 * TBUF;    // 2 x TBUF

    const int tid = threadIdx.x;
    const int m0 = blockIdx.x * 128;
    const int n0 = blockIdx.y * 128;
    const int NC = K / 16;

    const int rl = tid >> 2;       // load row 0..63
    const int k4 = tid & 3;        // k-quad within chunk

    {
        float4 a0 = *(const float4*)(A + (size_t)(m0 + rl) * K + k4 * 4);
        float4 a1 = *(const float4*)(A + (size_t)(m0 + rl + 64) * K + k4 * 4);
        float4 w0 = *(const float4*)(W + (size_t)(n0 + rl) * K + k4 * 4);
        float4 w1 = *(const float4*)(W + (size_t)(n0 + rl + 64) * K + k4 * 4);
        #pragma unroll
        for (int j = 0; j < 4; j++) {
            float av0 = (j==0)?a0.x:(j==1)?a0.y:(j==2)?a0.z:a0.w;
            float av1 = (j==0)?a1.x:(j==1)?a1.y:(j==2)?a1.z:a1.w;
            float wv0 = (j==0)?w0.x:(j==1)?w0.y:(j==2)?w0.z:w0.w;
            float wv1 = (j==0)?w1.x:(j==1)?w1.y:(j==2)?w1.z:w1.w;
            smA[(k4*4+j)*KPAD + rl]      = av0;
            smA[(k4*4+j)*KPAD + rl + 64] = av1;
            smW[(k4*4+j)*KPAD + rl]      = wv0;
            smW[(k4*4+j)*KPAD + rl + 64] = wv1;
        }
    }
    __syncthreads();

    const int mb = (tid >> 4) * 8;   // m-octet
    const int nb = (tid & 15) * 8;   // n-octet

    u64 acc[4][8];
    #pragma unroll
    for (int p = 0; p < 4; p++)
        #pragma unroll
        for (int j = 0; j < 8; j++) acc[p][j] = 0ull;

    int buf = 0;
    for (int c = 0; c < NC; c++) {
        float4 pa0, pa1, pw0, pw1;
        const bool pf = (c + 1 < NC);
        if (pf) {
            const int k0 = (c + 1) * 16;
            pa0 = *(const float4*)(A + (size_t)(m0 + rl) * K + k0 + k4 * 4);
            pa1 = *(const float4*)(A + (size_t)(m0 + rl + 64) * K + k0 + k4 * 4);
            pw0 = *(const float4*)(W + (size_t)(n0 + rl) * K + k0 + k4 * 4);
            pw1 = *(const float4*)(W + (size_t)(n0 + rl + 64) * K + k0 + k4 * 4);
        }

        const float* bA = smA + buf * TBUF;
        const float* bW = smW + buf * TBUF;
        #pragma unroll
        for (int kk = 0; kk < 16; kk++) {
            ulonglong2 aA = *(const ulonglong2*)(bA + kk * KPAD + mb);
            ulonglong2 aB = *(const ulonglong2*)(bA + kk * KPAD + mb + 4);
            float4 w0 = *(const float4*)(bW + kk * KPAD + nb);
            float4 w1 = *(const float4*)(bW + kk * KPAD + nb + 4);
            u64 ap[4] = {aA.x, aA.y, aB.x, aB.y};
            float wf[8] = {w0.x, w0.y, w0.z, w0.w, w1.x, w1.y, w1.z, w1.w};
            #pragma unroll
            for (int j = 0; j < 8; j++) {
                u64 wp = pack2(wf[j]);
                #pragma unroll
                for (int p = 0; p < 4; p++)
                    acc[p][j] = ffma2(ap[p], wp, acc[p][j]);
            }
        }

        if (pf) {
            float* dA = smA + (buf ^ 1) * TBUF;
            float* dW = smW + (buf ^ 1) * TBUF;
            #pragma unroll
            for (int j = 0; j < 4; j++) {
                float av0 = (j==0)?pa0.x:(j==1)?pa0.y:(j==2)?pa0.z:pa0.w;
                float av1 = (j==0)?pa1.x:(j==1)?pa1.y:(j==2)?pa1.z:pa1.w;
                float wv0 = (j==0)?pw0.x:(j==1)?pw0.y:(j==2)?pw0.z:pw0.w;
                float wv1 = (j==0)?pw1.x:(j==1)?pw1.y:(j==2)?pw1.z:pw1.w;
                dA[(k4*4+j)*KPAD + rl]      = av0;
                dA[(k4*4+j)*KPAD + rl + 64] = av1;
                dW[(k4*4+j)*KPAD + rl]      = wv0;
                dW[(k4*4+j)*KPAD + rl + 64] = wv1;
            }
        }
        __syncthreads();
        buf ^= 1;
    }

    float bias[8];
    #pragma unroll
    for (int j = 0; j < 8; j++)
        bias[j] = ba[n0 + nb + j] + bb[n0 + nb + j];

    #pragma unroll
    for (int p = 0; p < 4; p++) {
        float r0[8], r1[8];
        #pragma unroll
        for (int j = 0; j < 8; j++) {
            float2 v = unpack2(acc[p][j]);
            r0[j] = v.x + bias[j];
            r1[j] = v.y + bias[j];
        }
        float* o0 = out + (size_t)(m0 + mb + 2 * p) * GG + n0 + nb;
        float* o1 = o0 + GG;
        *(float4*)(o0)     = make_float4(r0[0], r0[1], r0[2], r0[3]);
        *(float4*)(o0 + 4) = make_float4(r0[4], r0[5], r0[6], r0[7]);
        *(float4*)(o1)     = make_float4(r1[0], r1[1], r1[2], r1[3]);
        *(float4*)(o1 + 4) = make_float4(r1[4], r1[5], r1[6], r1[7]);
    }
}

// =====================================================================
// Recurrent LSTM layer (FFMA2, W_hh in registers, COALESCED reduction).
// cluster = 2 CTAs, 8 batch rows per cluster; CTA owns 64 hidden cols
// (256 gate rows). Thread = 2 gate rows x 32 k (k-quarter): 64 W regs.
// Partials in gsm[kq][b][row] (coalesced STS/LDS, conflict-free).
// grid = 128 CTAs (64 clusters), block = 512.
// =====================================================================
__global__ void __cluster_dims__(2, 1, 1) __launch_bounds__(512, 1) lstm_kernel(
    const float* __restrict__ xp,    // [B, S, 4H]
    const float* __restrict__ W_hh,  // [4H, H]
    float* __restrict__ hseq,        // [B, S, H]  (layer 0)
    float* __restrict__ hlast,       // [B, H]     (layer 1)
    int store_seq)
{
    extern __shared__ float sm[];
    float* hsm = sm;          // 2 x [2 grp][128 k][4 b] = 2 x 1024
    float* gsm = sm + 2048;   // [4 kq][8 b][256 row] = 8192

    const int tid    = threadIdx.x;
    const int rank   = blockIdx.x & 1;
    const int peer   = rank ^ 1;
    const int batch0 = (blockIdx.x >> 1) * 8;

    const int kq = tid >> 7;         // k-quarter 0..3
    const int rr = tid & 127;        // local row-pair id
    const int grow0 = (rr >> 6) * 128 + rank * 64 + (rr & 63);
    const int grow1 = grow0 + 256;

    // ---- W slice into registers (once) ----
    float w0[32], w1[32];
    {
        const float4* p0 = (const float4*)(W_hh + (size_t)grow0 * HH + kq * 32);
        const float4* p1 = (const float4*)(W_hh + (size_t)grow1 * HH + kq * 32);
        #pragma unroll
        for (int j = 0; j < 8; j++) {
            float4 v0 = p0[j];
            float4 v1 = p1[j];
            w0[j * 4 + 0] = v0.x; w0[j * 4 + 1] = v0.y; w0[j * 4 + 2] = v0.z; w0[j * 4 + 3] = v0.w;
            w1[j * 4 + 0] = v1.x; w1[j * 4 + 1] = v1.y; w1[j * 4 + 2] = v1.z; w1[j * 4 + 3] = v1.w;
        }
    }
    for (int i = tid; i < 2048; i += 512) hsm[i] = 0.0f;

    asm volatile("barrier.cluster.arrive.aligned;\n" ::: "memory");
    asm volatile("barrier.cluster.wait.aligned;\n" ::: "memory");

    // update mapping: one (col, batch) per thread
    const int ub  = tid >> 6;        // batch 0..7
    const int ucl = tid & 63;        // local col
    const int col = rank * 64 + ucl;

    float creg = 0.0f;
    int buf = 0;

    for (int s = 0; s < SS; s++) {
        const float* Hc = hsm + buf * 1024 + kq * 128;  // this thread's k-quarter
        float* Hn = hsm + (buf ^ 1) * 1024;

        // prefetch x-projection (consumed in update phase)
        float xv0, xv1, xv2, xv3;
        {
            const float* xpp = xp + ((size_t)(batch0 + ub) * SS + s) * GG + rank * 64 + ucl;
            xv0 = xpp[0];
            xv1 = xpp[128];
            xv2 = xpp[256];
            xv3 = xpp[384];
        }

        // ---- partial gate GEMM: 2 rows x 32 k x 8 batch, W in regs
        u64 a00 = 0, a01 = 0, a02 = 0, a03 = 0;
        u64 a10 = 0, a11 = 0, a12 = 0, a13 = 0;

        #pragma unroll
        for (int k = 0; k < 32; k++) {
            ulonglong2 hA = *(const ulonglong2*)(Hc + k * 4);        // b0..b3 (broadcast)
            ulonglong2 hB = *(const ulonglong2*)(Hc + 512 + k * 4);  // b4..b7
            u64 wp0 = pack2(w0[k]);
            u64 wp1 = pack2(w1[k]);
            a00 = ffma2(hA.x, wp0, a00);
            a01 = ffma2(hA.y, wp0, a01);
            a02 = ffma2(hB.x, wp0, a02);
            a03 = ffma2(hB.y, wp0, a03);
            a10 = ffma2(hA.x, wp1, a10);
            a11 = ffma2(hA.y, wp1, a11);
            a12 = ffma2(hB.x, wp1, a12);
            a13 = ffma2(hB.y, wp1, a13);
        }

        // write partials COALESCED: gsm[kq][b][row], lanes -> consecutive rows
        {
            float* g0 = gsm + kq * 2048 + rr;          // row rr
            float* g1 = g0 + 128;                      // row rr+128
            float2 v;
            v = unpack2(a00); g0[0 * 256] = v.x; g0[1 * 256] = v.y;
            v = unpack2(a01); g0[2 * 256] = v.x; g0[3 * 256] = v.y;
            v = unpack2(a02); g0[4 * 256] = v.x; g0[5 * 256] = v.y;
            v = unpack2(a03); g0[6 * 256] = v.x; g0[7 * 256] = v.y;
            v = unpack2(a10); g1[0 * 256] = v.x; g1[1 * 256] = v.y;
            v = unpack2(a11); g1[2 * 256] = v.x; g1[3 * 256] = v.y;
            v = unpack2(a12); g1[4 * 256] = v.x; g1[5 * 256] = v.y;
            v = unpack2(a13); g1[6 * 256] = v.x; g1[7 * 256] = v.y;
        }
        __syncthreads();

        // ---- nonlinearity + state update: thread -> (col, batch ub)
        {
            float g4[4] = {xv0, xv1, xv2, xv3};
            #pragma unroll
            for (int gt = 0; gt < 4; gt++) {
                const int base = ub * 256 + gt * 64 + ucl;   // lanes -> consecutive rows
                g4[gt] += gsm[base];
                g4[gt] += gsm[2048 + base];
                g4[gt] += gsm[4096 + base];
                g4[gt] += gsm[6144 + base];
            }
            float iv = sigf(g4[0]);
            float fv = sigf(g4[1]);
            float gv = tanhf_fast(g4[2]);
            float ov = sigf(g4[3]);
            creg = fmaf(fv, creg, iv * gv);
            float hh = ov * tanhf_fast(creg);

            const int hoff = (ub >> 2) * 512 + col * 4 + (ub & 3);
            Hn[hoff] = hh;
            uint32_t la = (uint32_t)__cvta_generic_to_shared(Hn + hoff);
            uint32_t ra;
            asm("mapa.shared::cluster.u32 %0, %1, %2;" : "=r"(ra) : "r"(la), "r"(peer));
            asm volatile("st.shared::cluster.f32 [%0], %1;" :: "r"(ra), "f"(hh) : "memory");

            if (store_seq) {
                hseq[((size_t)(batch0 + ub) * SS + s) * HH + col] = hh;
            } else if (s == SS - 1) {
                hlast[(batch0 + ub) * HH + col] = hh;
            }
        }

        asm volatile("barrier.cluster.arrive.aligned;\n" ::: "memory");
        asm volatile("barrier.cluster.wait.aligned;\n" ::: "memory");
        buf ^= 1;
    }
}

// =====================================================================
// Final FC: out[b,o] = relu(h1[b,:]) @ fc_w[o,:] + fc_b[o]
// =====================================================================
__global__ __launch_bounds__(64) void fc_kernel(
    const float* __restrict__ h1, const float* __restrict__ fcw,
    const float* __restrict__ fcb, float* __restrict__ out)
{
    __shared__ float hs[HH];
    const int b = blockIdx.x;
    const int o = threadIdx.x;
    hs[o]      = fmaxf(h1[b * HH + o], 0.0f);
    hs[o + 64] = fmaxf(h1[b * HH + o + 64], 0.0f);
    __syncthreads();
    float acc = fcb[o];
    const float* wr = fcw + o * HH;
    #pragma unroll 8
    for (int k = 0; k < HH; k++)
        acc = fmaf(hs[k], wr[k], acc);
    out[b * OO + o] = acc;
}

// =====================================================================
extern "C" void kernel_launch(void* const* d_in, const int* in_sizes, int n_in,
                              void* d_out, int out_size)
{
    (void)in_sizes; (void)n_in; (void)out_size;
    const float* x     = (const float*)d_in[0];
    const float* W_ih0 = (const float*)d_in[1];
    const float* W_hh0 = (const float*)d_in[2];
    const float* b_ih0 = (const float*)d_in[3];
    const float* b_hh0 = (const float*)d_in[4];
    const float* W_ih1 = (const float*)d_in[5];
    const float* W_hh1 = (const float*)d_in[6];
    const float* b_ih1 = (const float*)d_in[7];
    const float* b_hh1 = (const float*)d_in[8];
    const float* fc_w  = (const float*)d_in[9];
    const float* fc_b  = (const float*)d_in[10];
    float* out = (float*)d_out;

    float *xp, *h0, *h1;
    cudaGetSymbolAddress((void**)&xp, g_xp);
    cudaGetSymbolAddress((void**)&h0, g_h0);
    cudaGetSymbolAddress((void**)&h1, g_h1);

    const int PROJ_SMEM = 4 * TBUF * 4;             // 34816
    const int LSTM_SMEM = (2048 + 8192) * 4;        // 40960

    cudaFuncSetAttribute(proj_kernel<FF>, cudaFuncAttributeMaxDynamicSharedMemorySize, PROJ_SMEM);
    cudaFuncSetAttribute(proj_kernel<HH>, cudaFuncAttributeMaxDynamicSharedMemorySize, PROJ_SMEM);
    cudaFuncSetAttribute(lstm_kernel, cudaFuncAttributeMaxDynamicSharedMemorySize, LSTM_SMEM);

    dim3 pgrid((BB * SS) / 128, GG / 128);

    // Layer 0
    proj_kernel<FF><<<pgrid, 256, PROJ_SMEM>>>(x, W_ih0, b_ih0, b_hh0, xp);
    lstm_kernel<<<128, 512, LSTM_SMEM>>>(xp, W_hh0, h0, nullptr, 1);

    // Layer 1
    proj_kernel<HH><<<pgrid, 256, PROJ_SMEM>>>(h0, W_ih1, b_ih1, b_hh1, xp);
    lstm_kernel<<<128, 512, LSTM_SMEM>>>(xp, W_hh1, nullptr, h1, 0);

    // FC head
    fc_kernel<<<BB, 64>>>(h1, fc_w, fc_b, out);
}